// round 1
// baseline (speedup 1.0000x reference)
#include <cuda_runtime.h>
#include <math.h>

// Problem constants (fixed by the dataset): B=2,S=2048 -> N=4096 tokens
#define NTOK 4096
#define DDIM 1024
#define NEXP 8
#define HDIM 4096
#define MTOT (NTOK * 2)   // total (token, expert-slot) assignments

// ---------------- device scratch (static: no allocations allowed) -----------
__device__ float g_hbuf[(size_t)MTOT * HDIM];  // fp32 intermediate h (134 MB)
__device__ int   g_perm[MTOT];                 // grouped row -> token index
__device__ float g_wgt[MTOT];                  // grouped row -> softmax weight
__device__ int   g_counts[NEXP];
__device__ int   g_offsets[NEXP + 1];
__device__ int   g_cursor[NEXP];
__device__ float g_enorm[NEXP];
__device__ int   g_tok_e[NTOK * 2];
__device__ float g_tok_w[NTOK * 2];

// ---------------- kernel 0: zero out + control state ------------------------
__global__ void k_zero(float* __restrict__ out, int out_n4)
{
    int i = blockIdx.x * blockDim.x + threadIdx.x;
    if (i < out_n4) {
        ((float4*)out)[i] = make_float4(0.f, 0.f, 0.f, 0.f);
    }
    if (blockIdx.x == 0 && threadIdx.x < NEXP) {
        g_counts[threadIdx.x] = 0;
        g_cursor[threadIdx.x] = 0;
    }
}

// ---------------- kernel 1: expert embedding norms ---------------------------
__global__ void k_enorm(const float* __restrict__ emb)
{
    __shared__ float red[256];
    int e = blockIdx.x;
    float s = 0.f;
    for (int k = threadIdx.x; k < DDIM; k += blockDim.x) {
        float v = emb[e * DDIM + k];
        s += v * v;
    }
    red[threadIdx.x] = s;
    __syncthreads();
    for (int off = 128; off > 0; off >>= 1) {
        if (threadIdx.x < off) red[threadIdx.x] += red[threadIdx.x + off];
        __syncthreads();
    }
    if (threadIdx.x == 0) g_enorm[e] = sqrtf(red[0]);
}

// ---------------- kernel 2: routing (one warp per token) --------------------
__global__ void k_route(const float* __restrict__ x,
                        const float* __restrict__ emb,
                        const float* __restrict__ cache)
{
    int tok  = blockIdx.x * (blockDim.x >> 5) + (threadIdx.x >> 5);
    int lane = threadIdx.x & 31;
    if (tok >= NTOK) return;

    const float* t = x + (size_t)tok * DDIM;
    float dot[NEXP];
#pragma unroll
    for (int e = 0; e < NEXP; e++) dot[e] = 0.f;
    float tsq = 0.f;

    for (int k = lane; k < DDIM; k += 32) {
        float tv = t[k];
        tsq += tv * tv;
#pragma unroll
        for (int e = 0; e < NEXP; e++) dot[e] += tv * emb[e * DDIM + k];
    }
#pragma unroll
    for (int off = 16; off > 0; off >>= 1) {
        tsq += __shfl_xor_sync(0xffffffffu, tsq, off);
#pragma unroll
        for (int e = 0; e < NEXP; e++)
            dot[e] += __shfl_xor_sync(0xffffffffu, dot[e], off);
    }

    if (lane == 0) {
        float tn = sqrtf(tsq) + 1e-8f;  // ||t|| + EPS

        // top-7 of 8 raw sims == exclude argmin; lax.top_k is stable
        // (lower index preferred among ties) so the EXCLUDED one is the
        // highest-index among tied minima -> use <= when scanning forward.
        int excl = 0;
        float mn = dot[0];
#pragma unroll
        for (int e = 1; e < NEXP; e++)
            if (dot[e] <= mn) { mn = dot[e]; excl = e; }

        float score[NEXP];
#pragma unroll
        for (int e = 0; e < NEXP; e++)
            score[e] = dot[e] / (tn * (g_enorm[e] + 1e-8f)) + 0.1f * cache[e];

        int i1 = -1, i2 = -1;
        float s1 = -1e30f, s2 = -1e30f;
#pragma unroll
        for (int e = 0; e < NEXP; e++) {
            if (e == excl) continue;
            float sc = score[e];
            if (sc > s1)      { s2 = s1; i2 = i1; s1 = sc; i1 = e; }
            else if (sc > s2) { s2 = sc; i2 = e; }
        }
        float w1 = 1.f / (1.f + expf(s2 - s1));  // softmax([s1,s2])
        float w2 = 1.f - w1;

        g_tok_e[2 * tok + 0] = i1;
        g_tok_e[2 * tok + 1] = i2;
        g_tok_w[2 * tok + 0] = w1;
        g_tok_w[2 * tok + 1] = w2;
        atomicAdd(&g_counts[i1], 1);
        atomicAdd(&g_counts[i2], 1);
    }
}

// ---------------- kernel 3: prefix offsets (trivial) -------------------------
__global__ void k_offsets()
{
    if (threadIdx.x == 0 && blockIdx.x == 0) {
        int acc = 0;
        for (int e = 0; e < NEXP; e++) {
            g_offsets[e] = acc;
            acc += g_counts[e];
        }
        g_offsets[NEXP] = acc;
    }
}

// ---------------- kernel 4: scatter tokens into expert-grouped order --------
__global__ void k_scatter()
{
    int idx = blockIdx.x * blockDim.x + threadIdx.x;
    if (idx >= NTOK * 2) return;
    int e = g_tok_e[idx];
    int pos = g_offsets[e] + atomicAdd(&g_cursor[e], 1);
    g_perm[pos] = idx >> 1;
    g_wgt[pos]  = g_tok_w[idx];
}

// ---------------- grouped GEMM 1: h = gelu(x[perm] @ W1[e] + b1[e]) ----------
// Tiles: 128x128x8, 256 threads, 8x8 per thread.
__global__ __launch_bounds__(256)
void k_gemm1(const float* __restrict__ x,
             const float* __restrict__ W1,
             const float* __restrict__ b1)
{
    const int e  = blockIdx.z;
    const int m0 = blockIdx.y * 128;
    const int n0 = blockIdx.x * 128;
    const int base = g_offsets[e];
    const int cnt  = g_offsets[e + 1] - base;
    if (m0 >= cnt) return;

    const float* B = W1 + (size_t)e * DDIM * HDIM;  // [D,H] row-major, ld=H

    __shared__ float As[8][128];
    __shared__ float Bs[8][128];

    const int tid  = threadIdx.x;
    const int arow = tid >> 1;          // 0..127
    const int acol = (tid & 1) * 4;     // 0 or 4
    const int brow = tid >> 5;          // 0..7
    const int bcol = (tid & 31) * 4;    // 0..124
    const int ty = tid >> 4;            // 0..15
    const int tx = tid & 15;            // 0..15

    const int lm = m0 + arow;
    const float* Arow = (lm < cnt) ? (x + (size_t)g_perm[base + lm] * DDIM)
                                   : nullptr;

    float acc[8][8];
#pragma unroll
    for (int i = 0; i < 8; i++)
#pragma unroll
        for (int j = 0; j < 8; j++) acc[i][j] = 0.f;

    for (int k0 = 0; k0 < DDIM; k0 += 8) {
        float4 av = Arow ? *(const float4*)(Arow + k0 + acol)
                         : make_float4(0.f, 0.f, 0.f, 0.f);
        float4 bv = *(const float4*)(B + (size_t)(k0 + brow) * HDIM + n0 + bcol);
        __syncthreads();
        As[acol + 0][arow] = av.x;
        As[acol + 1][arow] = av.y;
        As[acol + 2][arow] = av.z;
        As[acol + 3][arow] = av.w;
        *(float4*)&Bs[brow][bcol] = bv;
        __syncthreads();
#pragma unroll
        for (int kk = 0; kk < 8; kk++) {
            float ra[8], rb[8];
#pragma unroll
            for (int i = 0; i < 8; i++) ra[i] = As[kk][ty * 8 + i];
#pragma unroll
            for (int j = 0; j < 8; j++) rb[j] = Bs[kk][tx * 8 + j];
#pragma unroll
            for (int i = 0; i < 8; i++)
#pragma unroll
                for (int j = 0; j < 8; j++) acc[i][j] += ra[i] * rb[j];
        }
    }

#pragma unroll
    for (int i = 0; i < 8; i++) {
        int gm = m0 + ty * 8 + i;
        if (gm >= cnt) continue;
        size_t row = (size_t)(base + gm) * HDIM;
#pragma unroll
        for (int j = 0; j < 8; j++) {
            int n = n0 + tx * 8 + j;
            float v = acc[i][j] + b1[e * HDIM + n];
            // exact GELU: 0.5*v*(1+erf(v/sqrt(2)))
            v = 0.5f * v * (1.f + erff(v * 0.70710678118654752f));
            g_hbuf[row + n] = v;
        }
    }
}

// ---------------- grouped GEMM 2: out[tok] += w * (h @ W2[e] + b2[e]) -------
__global__ __launch_bounds__(256)
void k_gemm2(const float* __restrict__ W2,
             const float* __restrict__ b2,
             float* __restrict__ out)
{
    const int e  = blockIdx.z;
    const int m0 = blockIdx.y * 128;
    const int n0 = blockIdx.x * 128;
    const int base = g_offsets[e];
    const int cnt  = g_offsets[e + 1] - base;
    if (m0 >= cnt) return;

    const float* B = W2 + (size_t)e * HDIM * DDIM;  // [H,D] row-major, ld=D

    __shared__ float As[8][128];
    __shared__ float Bs[8][128];

    const int tid  = threadIdx.x;
    const int arow = tid >> 1;
    const int acol = (tid & 1) * 4;
    const int brow = tid >> 5;
    const int bcol = (tid & 31) * 4;
    const int ty = tid >> 4;
    const int tx = tid & 15;

    const int lm = m0 + arow;
    const float* Arow = (lm < cnt) ? (g_hbuf + (size_t)(base + lm) * HDIM)
                                   : nullptr;

    float acc[8][8];
#pragma unroll
    for (int i = 0; i < 8; i++)
#pragma unroll
        for (int j = 0; j < 8; j++) acc[i][j] = 0.f;

    for (int k0 = 0; k0 < HDIM; k0 += 8) {
        float4 av = Arow ? *(const float4*)(Arow + k0 + acol)
                         : make_float4(0.f, 0.f, 0.f, 0.f);
        float4 bv = *(const float4*)(B + (size_t)(k0 + brow) * DDIM + n0 + bcol);
        __syncthreads();
        As[acol + 0][arow] = av.x;
        As[acol + 1][arow] = av.y;
        As[acol + 2][arow] = av.z;
        As[acol + 3][arow] = av.w;
        *(float4*)&Bs[brow][bcol] = bv;
        __syncthreads();
#pragma unroll
        for (int kk = 0; kk < 8; kk++) {
            float ra[8], rb[8];
#pragma unroll
            for (int i = 0; i < 8; i++) ra[i] = As[kk][ty * 8 + i];
#pragma unroll
            for (int j = 0; j < 8; j++) rb[j] = Bs[kk][tx * 8 + j];
#pragma unroll
            for (int i = 0; i < 8; i++)
#pragma unroll
                for (int j = 0; j < 8; j++) acc[i][j] += ra[i] * rb[j];
        }
    }

#pragma unroll
    for (int i = 0; i < 8; i++) {
        int gm = m0 + ty * 8 + i;
        if (gm >= cnt) continue;
        int tok = g_perm[base + gm];
        float w = g_wgt[base + gm];
#pragma unroll
        for (int j = 0; j < 8; j++) {
            int n = n0 + tx * 8 + j;
            float v = acc[i][j] + b2[e * DDIM + n];
            atomicAdd(&out[(size_t)tok * DDIM + n], w * v);
        }
    }
}

// ---------------- launch ------------------------------------------------------
extern "C" void kernel_launch(void* const* d_in, const int* in_sizes, int n_in,
                              void* d_out, int out_size)
{
    const float* x     = (const float*)d_in[0];  // (2,2048,1024)
    const float* emb   = (const float*)d_in[1];  // (8,1024)
    const float* W1    = (const float*)d_in[2];  // (8,1024,4096)
    const float* b1    = (const float*)d_in[3];  // (8,4096)
    const float* W2    = (const float*)d_in[4];  // (8,4096,1024)
    const float* b2    = (const float*)d_in[5];  // (8,1024)
    const float* cache = (const float*)d_in[6];  // (8,)
    float* out = (float*)d_out;                  // (2,2048,1024) fp32

    // 0) zero output + counters
    int out_n4 = (NTOK * DDIM) / 4;
    k_zero<<<(out_n4 + 255) / 256, 256>>>(out, out_n4);

    // 1) expert embedding norms
    k_enorm<<<NEXP, 256>>>(emb);

    // 2) routing: 8 warps/block -> 8 tokens/block
    k_route<<<NTOK / 8, 256>>>(x, emb, cache);

    // 3) offsets
    k_offsets<<<1, 32>>>();

    // 4) scatter into grouped order
    k_scatter<<<(NTOK * 2 + 255) / 256, 256>>>();

    // 5) grouped GEMM1 + bias + gelu  (N=H=4096 -> 32 tiles; rows up to 4096)
    {
        dim3 grid(HDIM / 128, NTOK / 128, NEXP);
        k_gemm1<<<grid, 256>>>(x, W1, b1);
    }

    // 6) grouped GEMM2 + bias, weighted scatter-add
    {
        dim3 grid(DDIM / 128, NTOK / 128, NEXP);
        k_gemm2<<<grid, 256>>>(W2, b2, out);
    }
}

// round 3
// speedup vs baseline: 3.0722x; 3.0722x over previous
#include <cuda_runtime.h>
#include <math.h>
#include <stdint.h>

// Problem constants: B=2,S=2048 -> N=4096 tokens
#define NTOK 4096
#define DDIM 1024
#define NEXP 8
#define HDIM 4096
#define MTOT (NTOK * 2)   // total (token, expert-slot) rows = 8192 always
#define MPAD 128          // row padding so tile overreads stay in-bounds

// ---------------- device scratch (static; no allocations allowed) -----------
__device__ float g_hbuf[(size_t)(MTOT + MPAD) * HDIM];  // grouped h rows (tf32-rounded)
__device__ float g_xbuf[(size_t)(MTOT + MPAD) * DDIM];  // gathered x rows (tf32-rounded)
__device__ float g_w1r[(size_t)NEXP * DDIM * HDIM];     // W1 rounded to tf32
__device__ float g_w2r[(size_t)NEXP * HDIM * DDIM];     // W2 rounded to tf32
__device__ int   g_perm[MTOT + MPAD];
__device__ float g_wgt[MTOT + MPAD];
__device__ int   g_counts[NEXP];
__device__ int   g_offsets[NEXP + 1];
__device__ int   g_cursor[NEXP];
__device__ float g_enorm[NEXP];
__device__ int   g_tok_e[NTOK * 2];
__device__ float g_tok_w[NTOK * 2];

// ================= helpers ===================================================
__device__ __forceinline__ uint32_t smem_u32(const void* p) {
    uint32_t a;
    asm("{ .reg .u64 t; cvta.to.shared.u64 t, %1; cvt.u32.u64 %0, t; }" : "=r"(a) : "l"(p));
    return a;
}
__device__ __forceinline__ void cp16(uint32_t dst, const void* src) {
    asm volatile("cp.async.cg.shared.global [%0], [%1], 16;" :: "r"(dst), "l"(src) : "memory");
}
__device__ __forceinline__ void cp_commit() {
    asm volatile("cp.async.commit_group;" ::: "memory");
}
__device__ __forceinline__ float tf32r(float x) {
    float r;
    asm("cvt.rna.tf32.f32 %0, %1;" : "=f"(r) : "f"(x));
    return r;
}
__device__ __forceinline__ void mma_tf32(float c[4], const uint32_t a[4], const uint32_t b[2]) {
    asm volatile(
        "mma.sync.aligned.m16n8k8.row.col.f32.tf32.tf32.f32 "
        "{%0,%1,%2,%3}, {%4,%5,%6,%7}, {%8,%9}, {%0,%1,%2,%3};"
        : "+f"(c[0]), "+f"(c[1]), "+f"(c[2]), "+f"(c[3])
        : "r"(a[0]), "r"(a[1]), "r"(a[2]), "r"(a[3]), "r"(b[0]), "r"(b[1]));
}

// ================= small kernels =============================================
__global__ void k_zero(float* __restrict__ out, int out_n4)
{
    int i = blockIdx.x * blockDim.x + threadIdx.x;
    if (i < out_n4) ((float4*)out)[i] = make_float4(0.f, 0.f, 0.f, 0.f);
    if (blockIdx.x == 0 && threadIdx.x < NEXP) {
        g_counts[threadIdx.x] = 0;
        g_cursor[threadIdx.x] = 0;
    }
}

__global__ void k_enorm(const float* __restrict__ emb)
{
    __shared__ float red[256];
    int e = blockIdx.x;
    float s = 0.f;
    for (int k = threadIdx.x; k < DDIM; k += blockDim.x) {
        float v = emb[e * DDIM + k];
        s += v * v;
    }
    red[threadIdx.x] = s;
    __syncthreads();
    for (int off = 128; off > 0; off >>= 1) {
        if (threadIdx.x < off) red[threadIdx.x] += red[threadIdx.x + off];
        __syncthreads();
    }
    if (threadIdx.x == 0) g_enorm[e] = sqrtf(red[0]);
}

__global__ void k_route(const float* __restrict__ x,
                        const float* __restrict__ emb,
                        const float* __restrict__ cache)
{
    int tok  = blockIdx.x * (blockDim.x >> 5) + (threadIdx.x >> 5);
    int lane = threadIdx.x & 31;
    if (tok >= NTOK) return;

    const float* t = x + (size_t)tok * DDIM;
    float dot[NEXP];
#pragma unroll
    for (int e = 0; e < NEXP; e++) dot[e] = 0.f;
    float tsq = 0.f;
    for (int k = lane; k < DDIM; k += 32) {
        float tv = t[k];
        tsq += tv * tv;
#pragma unroll
        for (int e = 0; e < NEXP; e++) dot[e] += tv * emb[e * DDIM + k];
    }
#pragma unroll
    for (int off = 16; off > 0; off >>= 1) {
        tsq += __shfl_xor_sync(0xffffffffu, tsq, off);
#pragma unroll
        for (int e = 0; e < NEXP; e++)
            dot[e] += __shfl_xor_sync(0xffffffffu, dot[e], off);
    }
    if (lane == 0) {
        float tn = sqrtf(tsq) + 1e-8f;
        int excl = 0;
        float mn = dot[0];
#pragma unroll
        for (int e = 1; e < NEXP; e++)
            if (dot[e] <= mn) { mn = dot[e]; excl = e; }
        float score[NEXP];
#pragma unroll
        for (int e = 0; e < NEXP; e++)
            score[e] = dot[e] / (tn * (g_enorm[e] + 1e-8f)) + 0.1f * cache[e];
        int i1 = -1, i2 = -1;
        float s1 = -1e30f, s2 = -1e30f;
#pragma unroll
        for (int e = 0; e < NEXP; e++) {
            if (e == excl) continue;
            float sc = score[e];
            if (sc > s1)      { s2 = s1; i2 = i1; s1 = sc; i1 = e; }
            else if (sc > s2) { s2 = sc; i2 = e; }
        }
        float w1 = 1.f / (1.f + expf(s2 - s1));
        float w2 = 1.f - w1;
        g_tok_e[2 * tok + 0] = i1;
        g_tok_e[2 * tok + 1] = i2;
        g_tok_w[2 * tok + 0] = w1;
        g_tok_w[2 * tok + 1] = w2;
        atomicAdd(&g_counts[i1], 1);
        atomicAdd(&g_counts[i2], 1);
    }
}

__global__ void k_offsets()
{
    if (threadIdx.x == 0 && blockIdx.x == 0) {
        int acc = 0;
        for (int e = 0; e < NEXP; e++) { g_offsets[e] = acc; acc += g_counts[e]; }
        g_offsets[NEXP] = acc;
    }
}

__global__ void k_scatter()
{
    int idx = blockIdx.x * blockDim.x + threadIdx.x;
    if (idx >= NTOK * 2) return;
    int e = g_tok_e[idx];
    int pos = g_offsets[e] + atomicAdd(&g_cursor[e], 1);
    g_perm[pos] = idx >> 1;
    g_wgt[pos]  = g_tok_w[idx];
}

// gather x rows into grouped order, rounding to tf32
__global__ void k_gather(const float* __restrict__ x)
{
    int r = blockIdx.x;
    int t = g_perm[r];
    const float4* s = (const float4*)(x + (size_t)t * DDIM);
    float4* d = (float4*)(g_xbuf + (size_t)r * DDIM);
    float4 v = s[threadIdx.x];
    v.x = tf32r(v.x); v.y = tf32r(v.y); v.z = tf32r(v.z); v.w = tf32r(v.w);
    d[threadIdx.x] = v;
}

// round a big array to tf32 (copy)
__global__ void k_round(const float4* __restrict__ src, float4* __restrict__ dst, int n4)
{
    int i = blockIdx.x * blockDim.x + threadIdx.x;
    int stride = gridDim.x * blockDim.x;
    for (; i < n4; i += stride) {
        float4 v = src[i];
        v.x = tf32r(v.x); v.y = tf32r(v.y); v.z = tf32r(v.z); v.w = tf32r(v.w);
        dst[i] = v;
    }
}

// ================= tensor-core grouped GEMM (mma.sync tf32) ==================
// CTA tile 128(M) x 256(N), K-chunk 32, double-buffered cp.async.
// 8 warps in 2x4 grid; warp tile 64x64 (4 m-frags x 8 n-frags of m16n8k8).
// SMEM: A [128][40] padded (bank-free: 8r+c), B k-major [32][264] (8k+n).
#define ASTR 40
#define BSTR 264
#define A_FLOATS (128 * ASTR)               // per stage: 5120
#define B_FLOATS (32 * BSTR)                // per stage: 8448
#define SMEM_FLOATS (2 * (A_FLOATS + B_FLOATS))
#define SMEM_BYTES (SMEM_FLOATS * 4)

template<int KTOT, int NDIM, bool IS_G1>
__global__ __launch_bounds__(256)
void k_tc(const float* __restrict__ Asrc, const float* __restrict__ Bsrc,
          const float* __restrict__ bias, float* __restrict__ outp)
{
    const int e  = blockIdx.z;
    const int n0 = blockIdx.x * 256;
    const int m0 = blockIdx.y * 128;
    const int base = g_offsets[e];
    const int cnt  = g_offsets[e + 1] - base;
    if (m0 >= cnt) return;

    extern __shared__ float smf[];
    float* As = smf;                      // 2 stages of A
    float* Bs = smf + 2 * A_FLOATS;       // 2 stages of B
    const uint32_t sAu = smem_u32(As);
    const uint32_t sBu = smem_u32(Bs);

    const int tid  = threadIdx.x;
    const int wid  = tid >> 5, lane = tid & 31;
    const int wm   = wid >> 2, wn = wid & 3;    // warp grid 2x4
    const int lr   = lane >> 2, lc = lane & 3;

    const float* Abase = Asrc + (size_t)(base + m0) * KTOT;
    const float* Bbase = Bsrc + (size_t)e * KTOT * NDIM + n0;

    float acc[4][8][4];
#pragma unroll
    for (int i = 0; i < 4; i++)
#pragma unroll
        for (int j = 0; j < 8; j++)
#pragma unroll
            for (int k = 0; k < 4; k++) acc[i][j][k] = 0.f;

    constexpr int NC = KTOT / 32;

    // ---- async tile loader
    auto load_chunk = [&](int c) {
        const int s  = c & 1;
        const int k0 = c * 32;
#pragma unroll
        for (int i = 0; i < 4; i++) {           // A: 128x32 = 1024 float4
            int idx = tid + i * 256;
            int m = idx >> 3, k4 = idx & 7;
            cp16(sAu + (uint32_t)(s * A_FLOATS + m * ASTR + k4 * 4) * 4,
                 Abase + (size_t)m * KTOT + k0 + k4 * 4);
        }
#pragma unroll
        for (int i = 0; i < 8; i++) {           // B: 32x256 = 2048 float4
            int idx = tid + i * 256;
            int kr = idx >> 6, c4 = idx & 63;
            cp16(sBu + (uint32_t)(s * B_FLOATS + kr * BSTR + c4 * 4) * 4,
                 Bbase + (size_t)(k0 + kr) * NDIM + c4 * 4);
        }
        cp_commit();
    };

    load_chunk(0);

    for (int c = 0; c < NC; c++) {
        if (c + 1 < NC) {
            load_chunk(c + 1);
            asm volatile("cp.async.wait_group 1;" ::: "memory");
        } else {
            asm volatile("cp.async.wait_group 0;" ::: "memory");
        }
        __syncthreads();

        const float* Ab = As + (c & 1) * A_FLOATS;
        const float* Bb = Bs + (c & 1) * B_FLOATS;

#pragma unroll
        for (int kk = 0; kk < 4; kk++) {
            const int kr = kk * 8;
            uint32_t a[4][4], b[8][2];
#pragma unroll
            for (int mt = 0; mt < 4; mt++) {
                const float* p = Ab + (wm * 64 + mt * 16 + lr) * ASTR + kr + lc;
                a[mt][0] = __float_as_uint(p[0]);
                a[mt][1] = __float_as_uint(p[8 * ASTR]);
                a[mt][2] = __float_as_uint(p[4]);
                a[mt][3] = __float_as_uint(p[8 * ASTR + 4]);
            }
#pragma unroll
            for (int nt = 0; nt < 8; nt++) {
                const float* p = Bb + (kr + lc) * BSTR + wn * 64 + nt * 8 + lr;
                b[nt][0] = __float_as_uint(p[0]);
                b[nt][1] = __float_as_uint(p[4 * BSTR]);
            }
#pragma unroll
            for (int mt = 0; mt < 4; mt++)
#pragma unroll
                for (int nt = 0; nt < 8; nt++)
                    mma_tf32(acc[mt][nt], a[mt], b[nt]);
        }
        __syncthreads();
    }

    // ---- epilogue
#pragma unroll
    for (int mt = 0; mt < 4; mt++) {
        const int r0 = m0 + wm * 64 + mt * 16 + lr;
        const int r1 = r0 + 8;
        const bool v0 = r0 < cnt, v1 = r1 < cnt;
        int tok0 = 0, tok1 = 0;
        float wt0 = 0.f, wt1 = 0.f;
        if (!IS_G1) {
            tok0 = g_perm[base + r0]; wt0 = g_wgt[base + r0];
            tok1 = g_perm[base + r1]; wt1 = g_wgt[base + r1];
        }
#pragma unroll
        for (int nt = 0; nt < 8; nt++) {
            const int col = n0 + wn * 64 + nt * 8 + 2 * lc;
            const float bv0 = __ldg(bias + e * NDIM + col);
            const float bv1 = __ldg(bias + e * NDIM + col + 1);
            float c0 = acc[mt][nt][0] + bv0;
            float c1 = acc[mt][nt][1] + bv1;
            float c2 = acc[mt][nt][2] + bv0;
            float c3 = acc[mt][nt][3] + bv1;
            if (IS_G1) {
                // exact GELU then tf32-round (feeds GEMM2's A operand)
                c0 = tf32r(0.5f * c0 * (1.f + erff(c0 * 0.70710678118654752f)));
                c1 = tf32r(0.5f * c1 * (1.f + erff(c1 * 0.70710678118654752f)));
                c2 = tf32r(0.5f * c2 * (1.f + erff(c2 * 0.70710678118654752f)));
                c3 = tf32r(0.5f * c3 * (1.f + erff(c3 * 0.70710678118654752f)));
                if (v0) *(float2*)&outp[(size_t)(base + r0) * NDIM + col] = make_float2(c0, c1);
                if (v1) *(float2*)&outp[(size_t)(base + r1) * NDIM + col] = make_float2(c2, c3);
            } else {
                if (v0) {
                    atomicAdd(&outp[(size_t)tok0 * NDIM + col],     wt0 * c0);
                    atomicAdd(&outp[(size_t)tok0 * NDIM + col + 1], wt0 * c1);
                }
                if (v1) {
                    atomicAdd(&outp[(size_t)tok1 * NDIM + col],     wt1 * c2);
                    atomicAdd(&outp[(size_t)tok1 * NDIM + col + 1], wt1 * c3);
                }
            }
        }
    }
}

// ================= host side =================================================
extern "C" void kernel_launch(void* const* d_in, const int* in_sizes, int n_in,
                              void* d_out, int out_size)
{
    const float* x     = (const float*)d_in[0];
    const float* emb   = (const float*)d_in[1];
    const float* W1    = (const float*)d_in[2];
    const float* b1    = (const float*)d_in[3];
    const float* W2    = (const float*)d_in[4];
    const float* b2    = (const float*)d_in[5];
    const float* cache = (const float*)d_in[6];
    float* out = (float*)d_out;

    void *xbuf, *hbuf, *w1r, *w2r;
    cudaGetSymbolAddress(&xbuf, g_xbuf);
    cudaGetSymbolAddress(&hbuf, g_hbuf);
    cudaGetSymbolAddress(&w1r, g_w1r);
    cudaGetSymbolAddress(&w2r, g_w2r);

    cudaFuncSetAttribute(k_tc<DDIM, HDIM, true>,
                         cudaFuncAttributeMaxDynamicSharedMemorySize, SMEM_BYTES);
    cudaFuncSetAttribute(k_tc<HDIM, DDIM, false>,
                         cudaFuncAttributeMaxDynamicSharedMemorySize, SMEM_BYTES);

    // routing + grouping
    int out_n4 = (NTOK * DDIM) / 4;
    k_zero<<<(out_n4 + 255) / 256, 256>>>(out, out_n4);
    k_enorm<<<NEXP, 256>>>(emb);
    k_route<<<NTOK / 8, 256>>>(x, emb, cache);
    k_offsets<<<1, 32>>>();
    k_scatter<<<(NTOK * 2 + 255) / 256, 256>>>();
    k_gather<<<MTOT, 256>>>(x);

    // tf32-round weights (one copy each)
    int wn4 = NEXP * DDIM * HDIM / 4;
    k_round<<<8192, 256>>>((const float4*)W1, (float4*)w1r, wn4);
    k_round<<<8192, 256>>>((const float4*)W2, (float4*)w2r, wn4);

    // GEMM1: h = gelu(xbuf @ W1 + b1)   [K=1024, N=4096]
    {
        dim3 grid(HDIM / 256, NTOK / 128, NEXP);
        k_tc<DDIM, HDIM, true><<<grid, 256, SMEM_BYTES>>>(
            (const float*)xbuf, (const float*)w1r, b1, (float*)hbuf);
    }
    // GEMM2: out[tok] += w * (hbuf @ W2 + b2)   [K=4096, N=1024]
    {
        dim3 grid(DDIM / 256, NTOK / 128, NEXP);
        k_tc<HDIM, DDIM, false><<<grid, 256, SMEM_BYTES>>>(
            (const float*)hbuf, (const float*)w2r, b2, out);
    }
}

// round 4
// speedup vs baseline: 4.7019x; 1.5305x over previous
#include <cuda_runtime.h>
#include <cuda_fp16.h>
#include <math.h>
#include <stdint.h>

// Problem constants: B=2,S=2048 -> N=4096 tokens
#define NTOK 4096
#define DDIM 1024
#define NEXP 8
#define HDIM 4096
#define MTOT (NTOK * 2)
#define MPAD 128

// ---------------- device scratch (static; zero-initialized) -----------------
__device__ __half g_hbuf[(size_t)(MTOT + MPAD) * HDIM];  // grouped h rows (fp16)
__device__ __half g_xbuf[(size_t)(MTOT + MPAD) * DDIM];  // gathered x rows (fp16)
__device__ __half g_w1h[(size_t)NEXP * DDIM * HDIM];     // W1 fp16  [E][D][H]
__device__ __half g_w2h[(size_t)NEXP * HDIM * DDIM];     // W2 fp16  [E][H][D]
__device__ int    g_perm[MTOT + MPAD];
__device__ float  g_wgt[MTOT + MPAD];
__device__ int    g_counts[NEXP];
__device__ int    g_offsets[NEXP + 1];
__device__ int    g_cursor[NEXP];
__device__ float  g_enorm[NEXP];
__device__ int    g_tok_e[NTOK * 2];
__device__ float  g_tok_w[NTOK * 2];

// ================= helpers ===================================================
__device__ __forceinline__ uint32_t smem_u32(const void* p) {
    uint32_t a;
    asm("{ .reg .u64 t; cvta.to.shared.u64 t, %1; cvt.u32.u64 %0, t; }" : "=r"(a) : "l"(p));
    return a;
}
__device__ __forceinline__ void cp16(uint32_t dst, const void* src) {
    asm volatile("cp.async.cg.shared.global [%0], [%1], 16;" :: "r"(dst), "l"(src) : "memory");
}
__device__ __forceinline__ void cp_commit() {
    asm volatile("cp.async.commit_group;" ::: "memory");
}
__device__ __forceinline__ uint32_t pack2(float a, float b) {
    __half2 h = __floats2half2_rn(a, b);
    return *reinterpret_cast<uint32_t*>(&h);
}
__device__ __forceinline__ void ldm_x4(uint32_t r[4], uint32_t addr) {
    asm volatile("ldmatrix.sync.aligned.m8n8.x4.shared.b16 {%0,%1,%2,%3}, [%4];"
        : "=r"(r[0]), "=r"(r[1]), "=r"(r[2]), "=r"(r[3]) : "r"(addr));
}
__device__ __forceinline__ void ldm_x4t(uint32_t r[4], uint32_t addr) {
    asm volatile("ldmatrix.sync.aligned.m8n8.x4.trans.shared.b16 {%0,%1,%2,%3}, [%4];"
        : "=r"(r[0]), "=r"(r[1]), "=r"(r[2]), "=r"(r[3]) : "r"(addr));
}
__device__ __forceinline__ void mma_f16(float c[4], const uint32_t a[4],
                                        uint32_t b0, uint32_t b1) {
    asm volatile(
        "mma.sync.aligned.m16n8k16.row.col.f32.f16.f16.f32 "
        "{%0,%1,%2,%3}, {%4,%5,%6,%7}, {%8,%9}, {%0,%1,%2,%3};"
        : "+f"(c[0]), "+f"(c[1]), "+f"(c[2]), "+f"(c[3])
        : "r"(a[0]), "r"(a[1]), "r"(a[2]), "r"(a[3]), "r"(b0), "r"(b1));
}

// ================= small kernels =============================================
__global__ void k_zero(float* __restrict__ out, int out_n4)
{
    int i = blockIdx.x * blockDim.x + threadIdx.x;
    if (i < out_n4) ((float4*)out)[i] = make_float4(0.f, 0.f, 0.f, 0.f);
    if (blockIdx.x == 0 && threadIdx.x < NEXP) {
        g_counts[threadIdx.x] = 0;
        g_cursor[threadIdx.x] = 0;
    }
}

__global__ void k_enorm(const float* __restrict__ emb)
{
    __shared__ float red[256];
    int e = blockIdx.x;
    float s = 0.f;
    for (int k = threadIdx.x; k < DDIM; k += blockDim.x) {
        float v = emb[e * DDIM + k];
        s += v * v;
    }
    red[threadIdx.x] = s;
    __syncthreads();
    for (int off = 128; off > 0; off >>= 1) {
        if (threadIdx.x < off) red[threadIdx.x] += red[threadIdx.x + off];
        __syncthreads();
    }
    if (threadIdx.x == 0) g_enorm[e] = sqrtf(red[0]);
}

__global__ void k_route(const float* __restrict__ x,
                        const float* __restrict__ emb,
                        const float* __restrict__ cache)
{
    int tok  = blockIdx.x * (blockDim.x >> 5) + (threadIdx.x >> 5);
    int lane = threadIdx.x & 31;
    if (tok >= NTOK) return;

    const float* t = x + (size_t)tok * DDIM;
    float dot[NEXP];
#pragma unroll
    for (int e = 0; e < NEXP; e++) dot[e] = 0.f;
    float tsq = 0.f;
    for (int k = lane; k < DDIM; k += 32) {
        float tv = t[k];
        tsq += tv * tv;
#pragma unroll
        for (int e = 0; e < NEXP; e++) dot[e] += tv * emb[e * DDIM + k];
    }
#pragma unroll
    for (int off = 16; off > 0; off >>= 1) {
        tsq += __shfl_xor_sync(0xffffffffu, tsq, off);
#pragma unroll
        for (int e = 0; e < NEXP; e++)
            dot[e] += __shfl_xor_sync(0xffffffffu, dot[e], off);
    }
    if (lane == 0) {
        float tn = sqrtf(tsq) + 1e-8f;
        int excl = 0;
        float mn = dot[0];
#pragma unroll
        for (int e = 1; e < NEXP; e++)
            if (dot[e] <= mn) { mn = dot[e]; excl = e; }
        float score[NEXP];
#pragma unroll
        for (int e = 0; e < NEXP; e++)
            score[e] = dot[e] / (tn * (g_enorm[e] + 1e-8f)) + 0.1f * cache[e];
        int i1 = -1, i2 = -1;
        float s1 = -1e30f, s2 = -1e30f;
#pragma unroll
        for (int e = 0; e < NEXP; e++) {
            if (e == excl) continue;
            float sc = score[e];
            if (sc > s1)      { s2 = s1; i2 = i1; s1 = sc; i1 = e; }
            else if (sc > s2) { s2 = sc; i2 = e; }
        }
        float w1 = 1.f / (1.f + expf(s2 - s1));
        float w2 = 1.f - w1;
        g_tok_e[2 * tok + 0] = i1;
        g_tok_e[2 * tok + 1] = i2;
        g_tok_w[2 * tok + 0] = w1;
        g_tok_w[2 * tok + 1] = w2;
        atomicAdd(&g_counts[i1], 1);
        atomicAdd(&g_counts[i2], 1);
    }
}

__global__ void k_offsets()
{
    if (threadIdx.x == 0 && blockIdx.x == 0) {
        int acc = 0;
        for (int e = 0; e < NEXP; e++) { g_offsets[e] = acc; acc += g_counts[e]; }
        g_offsets[NEXP] = acc;
    }
}

__global__ void k_scatter()
{
    int idx = blockIdx.x * blockDim.x + threadIdx.x;
    if (idx >= NTOK * 2) return;
    int e = g_tok_e[idx];
    int pos = g_offsets[e] + atomicAdd(&g_cursor[e], 1);
    g_perm[pos] = idx >> 1;
    g_wgt[pos]  = g_tok_w[idx];
}

// gather x rows into grouped order, converting to fp16
__global__ void k_gather(const float* __restrict__ x)
{
    int r = blockIdx.x;
    int t = g_perm[r];
    const float4* s = (const float4*)(x + (size_t)t * DDIM);
    uint4* d = (uint4*)(g_xbuf + (size_t)r * DDIM);
    int i = threadIdx.x;                    // 128 threads x 8 floats
    float4 v0 = s[2 * i], v1 = s[2 * i + 1];
    uint4 o;
    o.x = pack2(v0.x, v0.y); o.y = pack2(v0.z, v0.w);
    o.z = pack2(v1.x, v1.y); o.w = pack2(v1.z, v1.w);
    d[i] = o;
}

// convert fp32 array -> fp16 (groups of 8)
__global__ void k_half(const float4* __restrict__ src, uint4* __restrict__ dst, int n8)
{
    int i = blockIdx.x * blockDim.x + threadIdx.x;
    int stride = gridDim.x * blockDim.x;
    for (; i < n8; i += stride) {
        float4 v0 = src[2 * i], v1 = src[2 * i + 1];
        uint4 o;
        o.x = pack2(v0.x, v0.y); o.y = pack2(v0.z, v0.w);
        o.z = pack2(v1.x, v1.y); o.w = pack2(v1.z, v1.w);
        dst[i] = o;
    }
}

// ================= fp16 tensor-core grouped GEMM =============================
// CTA tile 128(M) x 256(N), K-chunk 32, 4-stage cp.async pipeline.
// 8 warps 2x4; warp tile 64x64 (4 m-frags x 8 n-frags of m16n8k16).
// SMEM (halves): A [128][40], B k-major [32][264]  -> conflict-free ldmatrix.
#define ASTR 40
#define BSTR 264
#define A_HALVES (128 * ASTR)                 // 5120
#define B_HALVES (32 * BSTR)                  // 8448
#define STAGE_HALVES (A_HALVES + B_HALVES)    // 13568
#define STAGE_BYTES (STAGE_HALVES * 2)        // 27136
#define NSTAGE 4
#define SMEM_BYTES (NSTAGE * STAGE_BYTES)     // 108544

template<int KTOT, int NDIM, bool IS_G1>
__global__ __launch_bounds__(256)
void k_tc(const __half* __restrict__ Asrc, const __half* __restrict__ Bsrc,
          const float* __restrict__ bias, float* __restrict__ outp)
{
    const int e  = blockIdx.z;
    const int n0 = blockIdx.x * 256;
    const int m0 = blockIdx.y * 128;
    const int base = g_offsets[e];
    const int cnt  = g_offsets[e + 1] - base;
    if (m0 >= cnt) return;

    extern __shared__ __half smh[];
    const uint32_t s0 = smem_u32(smh);

    const int tid  = threadIdx.x;
    const int wid  = tid >> 5, lane = tid & 31;
    const int wm   = wid >> 2, wn = wid & 3;   // warp grid 2x4
    const int lr   = lane >> 2, lc = lane & 3;

    const __half* Abase = Asrc + (size_t)(base + m0) * KTOT;
    const __half* Bbase = Bsrc + (size_t)e * KTOT * NDIM + n0;

    float acc[4][8][4];
#pragma unroll
    for (int i = 0; i < 4; i++)
#pragma unroll
        for (int j = 0; j < 8; j++)
#pragma unroll
            for (int k = 0; k < 4; k++) acc[i][j][k] = 0.f;

    constexpr int NC = KTOT / 32;

    // per-thread cp.async assignments
    // A: 128x32 halves = 512x16B ; thread does 2
    const int am  = tid >> 1;                 // row 0..127
    const int aj  = (tid & 1) * 2;            // 16B-chunk 0..3 (2 each)
    // B: 32x256 halves = 1024x16B ; thread does 4
    const int bk  = tid >> 3;                 // k-row 0..31
    const int bj  = (tid & 7) * 4;            // 16B-chunk 0..31 (4 each)

    auto load_chunk = [&](int c) {
        const uint32_t sa = s0 + (uint32_t)(c & 3) * STAGE_BYTES;
        const uint32_t sb = sa + A_HALVES * 2;
        const int k0 = c * 32;
#pragma unroll
        for (int j = 0; j < 2; j++)
            cp16(sa + (uint32_t)(am * ASTR + (aj + j) * 8) * 2,
                 Abase + (size_t)am * KTOT + k0 + (aj + j) * 8);
#pragma unroll
        for (int j = 0; j < 4; j++)
            cp16(sb + (uint32_t)(bk * BSTR + (bj + j) * 8) * 2,
                 Bbase + (size_t)(k0 + bk) * NDIM + (bj + j) * 8);
        cp_commit();
    };

    load_chunk(0);
    load_chunk(1);
    load_chunk(2);

    // per-thread ldmatrix address bases (byte offsets within stage)
    const uint32_t a_off = (uint32_t)((wm * 64 + (lane & 15)) * ASTR + (lane >> 4) * 8) * 2;
    const uint32_t b_off = (uint32_t)(((lane & 7) + 8 * ((lane >> 3) & 1)) * BSTR
                                      + wn * 64 + 8 * (lane >> 4)) * 2 + A_HALVES * 2;

#pragma unroll 1
    for (int c = 0; c < NC; c++) {
        asm volatile("cp.async.wait_group 2;" ::: "memory");
        __syncthreads();
        if (c + 3 < NC) load_chunk(c + 3);
        else cp_commit();                      // keep group count uniform

        const uint32_t st = s0 + (uint32_t)(c & 3) * STAGE_BYTES;
#pragma unroll
        for (int kk = 0; kk < 2; kk++) {
            uint32_t a[4][4], b[4][4];
#pragma unroll
            for (int mt = 0; mt < 4; mt++)
                ldm_x4(a[mt], st + a_off + (uint32_t)(mt * 16 * ASTR + kk * 16) * 2);
#pragma unroll
            for (int np = 0; np < 4; np++)
                ldm_x4t(b[np], st + b_off + (uint32_t)(np * 16 + kk * 16 * BSTR) * 2);
#pragma unroll
            for (int mt = 0; mt < 4; mt++)
#pragma unroll
                for (int nt = 0; nt < 8; nt++)
                    mma_f16(acc[mt][nt], a[mt], b[nt >> 1][(nt & 1) * 2],
                            b[nt >> 1][(nt & 1) * 2 + 1]);
        }
    }

    // ---- epilogue
#pragma unroll
    for (int mt = 0; mt < 4; mt++) {
        const int r0 = m0 + wm * 64 + mt * 16 + lr;
        const int r1 = r0 + 8;
        const bool v0 = r0 < cnt, v1 = r1 < cnt;
        int tok0 = 0, tok1 = 0;
        float wt0 = 0.f, wt1 = 0.f;
        if (!IS_G1) {
            tok0 = g_perm[base + r0]; wt0 = g_wgt[base + r0];
            tok1 = g_perm[base + r1]; wt1 = g_wgt[base + r1];
        }
#pragma unroll
        for (int nt = 0; nt < 8; nt++) {
            const int col = n0 + wn * 64 + nt * 8 + 2 * lc;
            const float bv0 = __ldg(bias + e * NDIM + col);
            const float bv1 = __ldg(bias + e * NDIM + col + 1);
            float c0 = acc[mt][nt][0] + bv0;
            float c1 = acc[mt][nt][1] + bv1;
            float c2 = acc[mt][nt][2] + bv0;
            float c3 = acc[mt][nt][3] + bv1;
            if (IS_G1) {
                c0 = 0.5f * c0 * (1.f + erff(c0 * 0.70710678118654752f));
                c1 = 0.5f * c1 * (1.f + erff(c1 * 0.70710678118654752f));
                c2 = 0.5f * c2 * (1.f + erff(c2 * 0.70710678118654752f));
                c3 = 0.5f * c3 * (1.f + erff(c3 * 0.70710678118654752f));
                __half* hp = (__half*)outp;    // hbuf passed as float* alias
                if (v0) *(uint32_t*)&hp[(size_t)(base + r0) * NDIM + col] = pack2(c0, c1);
                if (v1) *(uint32_t*)&hp[(size_t)(base + r1) * NDIM + col] = pack2(c2, c3);
            } else {
                if (v0) {
                    atomicAdd(&outp[(size_t)tok0 * NDIM + col],     wt0 * c0);
                    atomicAdd(&outp[(size_t)tok0 * NDIM + col + 1], wt0 * c1);
                }
                if (v1) {
                    atomicAdd(&outp[(size_t)tok1 * NDIM + col],     wt1 * c2);
                    atomicAdd(&outp[(size_t)tok1 * NDIM + col + 1], wt1 * c3);
                }
            }
        }
    }
}

// ================= host side =================================================
extern "C" void kernel_launch(void* const* d_in, const int* in_sizes, int n_in,
                              void* d_out, int out_size)
{
    const float* x     = (const float*)d_in[0];
    const float* emb   = (const float*)d_in[1];
    const float* W1    = (const float*)d_in[2];
    const float* b1    = (const float*)d_in[3];
    const float* W2    = (const float*)d_in[4];
    const float* b2    = (const float*)d_in[5];
    const float* cache = (const float*)d_in[6];
    float* out = (float*)d_out;

    void *xbuf, *hbuf, *w1h, *w2h;
    cudaGetSymbolAddress(&xbuf, g_xbuf);
    cudaGetSymbolAddress(&hbuf, g_hbuf);
    cudaGetSymbolAddress(&w1h, g_w1h);
    cudaGetSymbolAddress(&w2h, g_w2h);

    cudaFuncSetAttribute(k_tc<DDIM, HDIM, true>,
                         cudaFuncAttributeMaxDynamicSharedMemorySize, SMEM_BYTES);
    cudaFuncSetAttribute(k_tc<HDIM, DDIM, false>,
                         cudaFuncAttributeMaxDynamicSharedMemorySize, SMEM_BYTES);

    // routing + grouping
    int out_n4 = (NTOK * DDIM) / 4;
    k_zero<<<(out_n4 + 255) / 256, 256>>>(out, out_n4);
    k_enorm<<<NEXP, 256>>>(emb);
    k_route<<<NTOK / 8, 256>>>(x, emb, cache);
    k_offsets<<<1, 32>>>();
    k_scatter<<<(NTOK * 2 + 255) / 256, 256>>>();
    k_gather<<<MTOT, 128>>>(x);

    // fp16 weight conversion
    int wn8 = NEXP * DDIM * HDIM / 8;
    k_half<<<4096, 256>>>((const float4*)W1, (uint4*)w1h, wn8);
    k_half<<<4096, 256>>>((const float4*)W2, (uint4*)w2h, wn8);

    // GEMM1: h = gelu(xbuf @ W1 + b1)   [K=1024, N=4096]
    {
        dim3 grid(HDIM / 256, NTOK / 128, NEXP);
        k_tc<DDIM, HDIM, true><<<grid, 256, SMEM_BYTES>>>(
            (const __half*)xbuf, (const __half*)w1h, b1, (float*)hbuf);
    }
    // GEMM2: out[tok] += w * (hbuf @ W2 + b2)   [K=4096, N=1024]
    {
        dim3 grid(DDIM / 256, NTOK / 128, NEXP);
        k_tc<HDIM, DDIM, false><<<grid, 256, SMEM_BYTES>>>(
            (const __half*)hbuf, (const __half*)w2h, b2, out);
    }
}